// round 5
// baseline (speedup 1.0000x reference)
#include <cuda_runtime.h>
#include <cstdint>

// Problem constants
constexpr int BATCH = 32;
constexpr int NT    = 320;   // template tokens
constexpr int LX    = 704;
constexpr int CH    = 768;
constexpr int TMPL  = 128;
constexpr int NS    = LX - TMPL;   // 576 keys

constexpr long long Q_ELEMS  = (long long)BATCH * NT * CH;   // 7,864,320
constexpr long long KV_ELEMS = (long long)BATCH * NS * CH;   // 14,155,776
constexpr long long S_ELEMS  = (long long)BATCH * NT * NS;   // 5,898,240
constexpr long long R_ELEMS  = (long long)BATCH * NS;        // 18,432

constexpr long long OFF_Q  = 0;
constexpr long long OFF_K  = OFF_Q  + Q_ELEMS;
constexpr long long OFF_KI = OFF_K  + KV_ELEMS;
constexpr long long OFF_V  = OFF_KI + KV_ELEMS;
constexpr long long OFF_VI = OFF_V  + KV_ELEMS;
constexpr long long OFF_S  = OFF_VI + KV_ELEMS;
constexpr long long OFF_SI = OFF_S  + S_ELEMS;
constexpr long long OFF_P  = OFF_SI + S_ELEMS;
constexpr long long OFF_U  = OFF_P  + Q_ELEMS;
constexpr long long OFF_S1 = OFF_U  + Q_ELEMS;
constexpr long long OFF_S2 = OFF_S1 + R_ELEMS;
constexpr long long SCRATCH_TOTAL = OFF_S2 + R_ELEMS;  // ~92.05M floats (~368 MB)

__device__ float g_scratch[SCRATCH_TOTAL];

// ---------------------------------------------------------------------------
// Tiled fp32 GEMM: 128x128 block tile, BK=8, 256 threads, 8x8 per thread.
// TRANSB: C[m,n] = sum_k A[m,k] * B[n,k]   (B row-major N x K)
// GATHER: A row r maps to source row (r/rpb)*srpb + roff + r%rpb
// Epilogue: C = alpha*acc + beta*C_old + (D ? D : 0)
// ---------------------------------------------------------------------------
constexpr int BM = 128, BN = 128, BK = 8;

template<bool TRANSB, bool GATHER>
__global__ __launch_bounds__(256)
void sgemm(const float* __restrict__ Ag, const float* __restrict__ Bg,
           float* __restrict__ Cg, const float* __restrict__ Dg,
           int M, int N, int K, int lda, int ldb, int ldc,
           long long sA, long long sB, long long sC,
           int rpb, int srpb, int roff,
           float alpha, float beta)
{
    __shared__ __align__(16) float As[BK][BM];
    __shared__ __align__(16) float Bs[BK][BN];

    const int tid = threadIdx.x;
    const int bz  = blockIdx.z;
    const float* A = Ag + bz * sA;
    const float* B = Bg + bz * sB;
    float*       C = Cg + bz * sC;
    const float* D = Dg;  // only used non-batched

    const int rowBase = blockIdx.y * BM;
    const int colBase = blockIdx.x * BN;

    // A tile load mapping: each thread one float4 of a 128x8 tile
    const int arow = tid >> 1;            // 0..127
    const int ak   = (tid & 1) * 4;       // 0 or 4
    const int gr   = rowBase + arow;
    const bool avalid = (gr < M);
    long long aoff = 0;
    if (avalid) {
        int src = gr;
        if (GATHER) src = (gr / rpb) * srpb + roff + (gr % rpb);
        aoff = (long long)src * lda + ak;
    }

    // B tile load mapping
    int brow, bcol; bool bvalid; long long boff = 0;
    if (!TRANSB) {
        brow = tid >> 5;                  // k-row 0..7
        bcol = (tid & 31) * 4;            // 0..124
        bvalid = (colBase + bcol) < N;
        if (bvalid) boff = (long long)brow * ldb + colBase + bcol;
    } else {
        brow = tid >> 1;                  // n index 0..127
        bcol = (tid & 1) * 4;             // k offset 0 or 4
        bvalid = (colBase + brow) < N;
        if (bvalid) boff = (long long)(colBase + brow) * ldb + bcol;
    }

    const int tx = tid & 15, ty = tid >> 4;

    float acc[8][8];
#pragma unroll
    for (int i = 0; i < 8; i++)
#pragma unroll
        for (int j = 0; j < 8; j++) acc[i][j] = 0.f;

    for (int k0 = 0; k0 < K; k0 += BK) {
        float4 a4 = make_float4(0.f, 0.f, 0.f, 0.f);
        if (avalid) a4 = *reinterpret_cast<const float4*>(A + aoff + k0);
        float4 b4 = make_float4(0.f, 0.f, 0.f, 0.f);
        if (!TRANSB) {
            if (bvalid) b4 = *reinterpret_cast<const float4*>(B + boff + (long long)k0 * ldb);
        } else {
            if (bvalid) b4 = *reinterpret_cast<const float4*>(B + boff + k0);
        }
        __syncthreads();   // previous tile's compute done
        As[ak + 0][arow] = a4.x; As[ak + 1][arow] = a4.y;
        As[ak + 2][arow] = a4.z; As[ak + 3][arow] = a4.w;
        if (!TRANSB) {
            *reinterpret_cast<float4*>(&Bs[brow][bcol]) = b4;
        } else {
            Bs[bcol + 0][brow] = b4.x; Bs[bcol + 1][brow] = b4.y;
            Bs[bcol + 2][brow] = b4.z; Bs[bcol + 3][brow] = b4.w;
        }
        __syncthreads();

#pragma unroll
        for (int kk = 0; kk < BK; kk++) {
            float4 a0 = *reinterpret_cast<const float4*>(&As[kk][ty * 4]);
            float4 a1 = *reinterpret_cast<const float4*>(&As[kk][64 + ty * 4]);
            float4 b0 = *reinterpret_cast<const float4*>(&Bs[kk][tx * 4]);
            float4 b1 = *reinterpret_cast<const float4*>(&Bs[kk][64 + tx * 4]);
            float a[8] = {a0.x, a0.y, a0.z, a0.w, a1.x, a1.y, a1.z, a1.w};
            float b[8] = {b0.x, b0.y, b0.z, b0.w, b1.x, b1.y, b1.z, b1.w};
#pragma unroll
            for (int i = 0; i < 8; i++)
#pragma unroll
                for (int j = 0; j < 8; j++)
                    acc[i][j] = fmaf(a[i], b[j], acc[i][j]);
        }
    }

    // Epilogue
#pragma unroll
    for (int ih = 0; ih < 2; ih++) {
#pragma unroll
        for (int ii = 0; ii < 4; ii++) {
            int r = rowBase + ih * 64 + ty * 4 + ii;
            if (r >= M) continue;
            int i = ih * 4 + ii;
#pragma unroll
            for (int jh = 0; jh < 2; jh++) {
                int c = colBase + jh * 64 + tx * 4;
                if (c >= N) continue;
                long long off = (long long)r * ldc + c;
                float4 res;
                res.x = alpha * acc[i][jh * 4 + 0];
                res.y = alpha * acc[i][jh * 4 + 1];
                res.z = alpha * acc[i][jh * 4 + 2];
                res.w = alpha * acc[i][jh * 4 + 3];
                if (beta != 0.f) {
                    float4 o = *reinterpret_cast<const float4*>(C + off);
                    res.x += beta * o.x; res.y += beta * o.y;
                    res.z += beta * o.z; res.w += beta * o.w;
                }
                if (D) {
                    float4 d4 = *reinterpret_cast<const float4*>(D + off);
                    res.x += d4.x; res.y += d4.y; res.z += d4.z; res.w += d4.w;
                }
                *reinterpret_cast<float4*>(C + off) = res;
            }
        }
    }
}

// ---------------------------------------------------------------------------
// Block reductions (256 threads)
// ---------------------------------------------------------------------------
__device__ __forceinline__ float block_reduce_max(float v) {
    __shared__ float red[8];
    int lane = threadIdx.x & 31, wid = threadIdx.x >> 5;
#pragma unroll
    for (int o = 16; o; o >>= 1) v = fmaxf(v, __shfl_xor_sync(0xffffffffu, v, o));
    if (lane == 0) red[wid] = v;
    __syncthreads();
    if (wid == 0) {
        v = (lane < 8) ? red[lane] : -3.4e38f;
#pragma unroll
        for (int o = 4; o; o >>= 1) v = fmaxf(v, __shfl_xor_sync(0xffffffffu, v, o));
        if (lane == 0) red[0] = v;
    }
    __syncthreads();
    v = red[0];
    __syncthreads();
    return v;
}

__device__ __forceinline__ float block_reduce_sum(float v) {
    __shared__ float red[8];
    int lane = threadIdx.x & 31, wid = threadIdx.x >> 5;
#pragma unroll
    for (int o = 16; o; o >>= 1) v += __shfl_xor_sync(0xffffffffu, v, o);
    if (lane == 0) red[wid] = v;
    __syncthreads();
    if (wid == 0) {
        v = (lane < 8) ? red[lane] : 0.f;
#pragma unroll
        for (int o = 4; o; o >>= 1) v += __shfl_xor_sync(0xffffffffu, v, o);
        if (lane == 0) red[0] = v;
    }
    __syncthreads();
    v = red[0];
    __syncthreads();
    return v;
}

// ---------------------------------------------------------------------------
// Row softmax over 576 columns, in place. grid = B*NT rows, block = 256
// ---------------------------------------------------------------------------
__global__ __launch_bounds__(256) void softmax_kernel(float* __restrict__ S) {
    const int cols = NS;
    long long base = (long long)blockIdx.x * cols;
    __shared__ float buf[NS];
    int tid = threadIdx.x;
    float m = -3.4e38f;
    for (int c = tid; c < cols; c += 256) {
        float v = S[base + c]; buf[c] = v; m = fmaxf(m, v);
    }
    m = block_reduce_max(m);
    float s = 0.f;
    for (int c = tid; c < cols; c += 256) {
        float e = expf(buf[c] - m); buf[c] = e; s += e;
    }
    s = block_reduce_sum(s);
    float inv = 1.f / s;
    for (int c = tid; c < cols; c += 256) S[base + c] = buf[c] * inv;
}

// ---------------------------------------------------------------------------
// Per-(b,n) sign counts over t: s1 = rgb+eq, s2 = 1-rgb (= tir+eq)
// ---------------------------------------------------------------------------
__global__ __launch_bounds__(256) void ratio_kernel(const float* __restrict__ S,
                                                    const float* __restrict__ Si,
                                                    float* __restrict__ s1,
                                                    float* __restrict__ s2) {
    int idx = blockIdx.x * blockDim.x + threadIdx.x;
    if (idx >= BATCH * NS) return;
    int b = idx / NS, n = idx - b * NS;
    const float* a  = S  + (long long)b * NT * NS + n;
    const float* ai = Si + (long long)b * NT * NS + n;
    int pos = 0, eq = 0;
    for (int t = 0; t < NT; t++) {
        float x = a[(long long)t * NS];
        float y = ai[(long long)t * NS];
        pos += (x > y);
        eq  += (x == y);
    }
    float rgb = pos * (1.f / NT);
    float eqr = eq  * (1.f / NT);
    s1[idx] = rgb + eqr;
    s2[idx] = 1.f - rgb;
}

// ---------------------------------------------------------------------------
// x_s = v * s1[row] + vi * s2[row]  -> out[0 : B*NS*CH]
// ---------------------------------------------------------------------------
__global__ __launch_bounds__(256) void xs_kernel(const float* __restrict__ V,
                                                 const float* __restrict__ VI,
                                                 const float* __restrict__ s1,
                                                 const float* __restrict__ s2,
                                                 float* __restrict__ out) {
    long long i = (long long)blockIdx.x * blockDim.x + threadIdx.x;
    const long long total4 = KV_ELEMS / 4;
    if (i >= total4) return;
    int row = (int)((i * 4) / CH);
    float a = s1[row], b = s2[row];
    float4 v4 = reinterpret_cast<const float4*>(V)[i];
    float4 w4 = reinterpret_cast<const float4*>(VI)[i];
    float4 r;
    r.x = v4.x * a + w4.x * b;
    r.y = v4.y * a + w4.y * b;
    r.z = v4.z * a + w4.z * b;
    r.w = v4.w * a + w4.w * b;
    reinterpret_cast<float4*>(out)[i] = r;
}

// ---------------------------------------------------------------------------
// LayerNorm over last dim (768). grid = B*NT rows, block = 256
// ---------------------------------------------------------------------------
__global__ __launch_bounds__(256) void ln_kernel(const float* __restrict__ U,
                                                 const float* __restrict__ gamma,
                                                 const float* __restrict__ beta,
                                                 float* __restrict__ out) {
    long long base = (long long)blockIdx.x * CH;
    __shared__ float buf[CH];
    int tid = threadIdx.x;
    float s = 0.f;
    for (int c = tid; c < CH; c += 256) {
        float v = U[base + c]; buf[c] = v; s += v;
    }
    s = block_reduce_sum(s);
    float mu = s * (1.f / CH);
    float vs = 0.f;
    for (int c = tid; c < CH; c += 256) {
        float d = buf[c] - mu; vs += d * d;
    }
    vs = block_reduce_sum(vs);
    float inv = rsqrtf(vs * (1.f / CH) + 1e-5f);
    for (int c = tid; c < CH; c += 256)
        out[base + c] = (buf[c] - mu) * inv * gamma[c] + beta[c];
}

// ---------------------------------------------------------------------------
// Launcher
// ---------------------------------------------------------------------------
extern "C" void kernel_launch(void* const* d_in, const int* in_sizes, int n_in,
                              void* d_out, int out_size) {
    const float* T     = (const float*)d_in[0];
    const float* x     = (const float*)d_in[1];
    const float* xi    = (const float*)d_in[2];
    const float* Wq    = (const float*)d_in[3];
    const float* Wk    = (const float*)d_in[4];
    const float* Wv    = (const float*)d_in[5];
    const float* Wout  = (const float*)d_in[6];
    const float* gamma = (const float*)d_in[7];
    const float* beta  = (const float*)d_in[8];
    float* out = (float*)d_out;

    void* sp = nullptr;
    cudaGetSymbolAddress(&sp, g_scratch);
    float* s = (float*)sp;
    float* Q  = s + OFF_Q;
    float* K  = s + OFF_K;
    float* KI = s + OFF_KI;
    float* V  = s + OFF_V;
    float* VI = s + OFF_VI;
    float* S  = s + OFF_S;
    float* SI = s + OFF_SI;
    float* P  = s + OFF_P;
    float* U  = s + OFF_U;
    float* S1 = s + OFF_S1;
    float* S2 = s + OFF_S2;

    const float scale = 1.0f / sqrtf((float)CH);
    const int MQ = BATCH * NT;   // 10240
    const int MK = BATCH * NS;   // 18432

    auto grid = [](int M, int N, int Z) {
        return dim3((unsigned)((N + BN - 1) / BN), (unsigned)((M + BM - 1) / BM), (unsigned)Z);
    };

    // 1) q = T @ Wq
    sgemm<false, false><<<grid(MQ, CH, 1), 256>>>(
        T, Wq, Q, nullptr, MQ, CH, CH, CH, CH, CH, 0, 0, 0, 0, 0, 0, 1.f, 0.f);
    // 2-5) k, ki, v, vi from gathered xs/xis rows
    sgemm<false, true><<<grid(MK, CH, 1), 256>>>(
        x, Wk, K, nullptr, MK, CH, CH, CH, CH, CH, 0, 0, 0, NS, LX, TMPL, 1.f, 0.f);
    sgemm<false, true><<<grid(MK, CH, 1), 256>>>(
        xi, Wk, KI, nullptr, MK, CH, CH, CH, CH, CH, 0, 0, 0, NS, LX, TMPL, 1.f, 0.f);
    sgemm<false, true><<<grid(MK, CH, 1), 256>>>(
        x, Wv, V, nullptr, MK, CH, CH, CH, CH, CH, 0, 0, 0, NS, LX, TMPL, 1.f, 0.f);
    sgemm<false, true><<<grid(MK, CH, 1), 256>>>(
        xi, Wv, VI, nullptr, MK, CH, CH, CH, CH, CH, 0, 0, 0, NS, LX, TMPL, 1.f, 0.f);

    // 6-7) S = scale * q @ k^T (batched), Si likewise
    sgemm<true, false><<<grid(NT, NS, BATCH), 256>>>(
        Q, K, S, nullptr, NT, NS, CH, CH, CH, NS,
        (long long)NT * CH, (long long)NS * CH, (long long)NT * NS,
        0, 0, 0, scale, 0.f);
    sgemm<true, false><<<grid(NT, NS, BATCH), 256>>>(
        Q, KI, SI, nullptr, NT, NS, CH, CH, CH, NS,
        (long long)NT * CH, (long long)NS * CH, (long long)NT * NS,
        0, 0, 0, scale, 0.f);

    // 8-9) row softmax in place
    softmax_kernel<<<MQ, 256>>>(S);
    softmax_kernel<<<MQ, 256>>>(SI);

    // 10) sign-count ratios
    ratio_kernel<<<(BATCH * NS + 255) / 256, 256>>>(S, SI, S1, S2);

    // 11) x_s -> out[0 : KV_ELEMS]
    xs_kernel<<<(unsigned)(KV_ELEMS / 4 / 256), 256>>>(V, VI, S1, S2, out);

    // 12-13) P = aw @ v + awi @ vi (batched, second accumulates)
    sgemm<false, false><<<grid(NT, CH, BATCH), 256>>>(
        S, V, P, nullptr, NT, CH, NS, NS, CH, CH,
        (long long)NT * NS, (long long)NS * CH, (long long)NT * CH,
        0, 0, 0, 1.f, 0.f);
    sgemm<false, false><<<grid(NT, CH, BATCH), 256>>>(
        SI, VI, P, nullptr, NT, CH, NS, NS, CH, CH,
        (long long)NT * NS, (long long)NS * CH, (long long)NT * CH,
        0, 0, 0, 1.f, 1.f);

    // 14) U = P @ Wout + T  (single shared-Wout GEMM with additive epilogue)
    sgemm<false, false><<<grid(MQ, CH, 1), 256>>>(
        P, Wout, U, T, MQ, CH, CH, CH, CH, CH, 0, 0, 0, 0, 0, 0, 1.f, 0.f);

    // 15) T_new = LayerNorm(U) -> out[KV_ELEMS : ]
    ln_kernel<<<MQ, 256>>>(U, gamma, beta, out + KV_ELEMS);
}

// round 10
// speedup vs baseline: 1.8730x; 1.8730x over previous
#include <cuda_runtime.h>
#include <cuda_bf16.h>
#include <cstdint>
#include <cmath>

using bf16 = __nv_bfloat16;

// ---------------------------------------------------------------------------
// Problem constants
// ---------------------------------------------------------------------------
constexpr int BATCH = 32, NT = 320, LX = 704, CH = 768, TMPL = 128;
constexpr int NS = LX - TMPL;          // 576
constexpr int MQ = BATCH * NT;         // 10240
constexpr int MK = BATCH * NS;         // 18432

constexpr size_t SZ_T  = (size_t)MQ * CH;        // 7,864,320
constexpr size_t SZ_W  = (size_t)CH * CH;        // 589,824
constexpr size_t SZ_X  = (size_t)MK * CH;        // 14,155,776
constexpr size_t SZ_S  = (size_t)BATCH * NT * NS;// 5,898,240
constexpr size_t SZ_R  = (size_t)BATCH * NS;     // 18,432

// bf16 pool: each logical tensor stores hi at O, lo at O+SZ
constexpr size_t O_T   = 0;
constexpr size_t O_WQ  = O_T   + 2 * SZ_T;
constexpr size_t O_WK  = O_WQ  + 2 * SZ_W;
constexpr size_t O_WV  = O_WK  + 2 * SZ_W;
constexpr size_t O_WO  = O_WV  + 2 * SZ_W;
constexpr size_t O_XS  = O_WO  + 2 * SZ_W;
constexpr size_t O_XIS = O_XS  + 2 * SZ_X;
constexpr size_t O_Q   = O_XIS + 2 * SZ_X;
constexpr size_t O_K   = O_Q   + 2 * SZ_T;
constexpr size_t O_KI  = O_K   + 2 * SZ_X;
constexpr size_t O_VT  = O_KI  + 2 * SZ_X;
constexpr size_t O_VIT = O_VT  + 2 * SZ_X;
constexpr size_t O_SH  = O_VIT + 2 * SZ_X;
constexpr size_t O_SIH = O_SH  + 2 * SZ_S;
constexpr size_t O_P   = O_SIH + 2 * SZ_S;
constexpr size_t BF_TOTAL = O_P + 2 * SZ_T;

// fp32 pool
constexpr size_t F_S  = 0;
constexpr size_t F_SI = F_S  + SZ_S;
constexpr size_t F_U  = F_SI + SZ_S;
constexpr size_t F_S1 = F_U  + SZ_T;
constexpr size_t F_S2 = F_S1 + SZ_R;
constexpr size_t F_TOTAL = F_S2 + SZ_R;

__device__ bf16  g_bf[BF_TOTAL];
__device__ float g_f[F_TOTAL];

// ---------------------------------------------------------------------------
// PTX helpers (sm_80-level only: cp.async, ldmatrix, mma.sync — all legal on
// the harness's compute_103 PTX target, unlike tcgen05/*a features)
// ---------------------------------------------------------------------------
__device__ __forceinline__ uint32_t smem_u32(const void* p) {
    uint32_t a;
    asm("{ .reg .u64 t; cvta.to.shared.u64 t, %1; cvt.u32.u64 %0, t; }"
        : "=r"(a) : "l"(p));
    return a;
}

__device__ __forceinline__ void cp16(uint32_t dst, const void* src, bool pred) {
    int sz = pred ? 16 : 0;
    asm volatile("cp.async.cg.shared.global [%0], [%1], 16, %2;"
                 :: "r"(dst), "l"(src), "r"(sz));
}
#define CP_COMMIT() asm volatile("cp.async.commit_group;" ::: "memory")
#define CP_WAIT(N)  asm volatile("cp.async.wait_group %0;" :: "n"(N) : "memory")

__device__ __forceinline__ void ldm_x4(uint32_t* r, uint32_t addr) {
    asm volatile("ldmatrix.sync.aligned.m8n8.x4.shared.b16 {%0,%1,%2,%3}, [%4];"
                 : "=r"(r[0]), "=r"(r[1]), "=r"(r[2]), "=r"(r[3]) : "r"(addr));
}

__device__ __forceinline__ void mma_bf16(float* c, const uint32_t* a, const uint32_t* b) {
    asm volatile(
        "mma.sync.aligned.m16n8k16.row.col.f32.bf16.bf16.f32 "
        "{%0,%1,%2,%3}, {%4,%5,%6,%7}, {%8,%9}, {%0,%1,%2,%3};"
        : "+f"(c[0]), "+f"(c[1]), "+f"(c[2]), "+f"(c[3])
        : "r"(a[0]), "r"(a[1]), "r"(a[2]), "r"(a[3]), "r"(b[0]), "r"(b[1]));
}

__device__ __forceinline__ void split2(float x, bf16& h, bf16& l) {
    h = __float2bfloat16(x);
    l = __float2bfloat16(x - __bfloat162float(h));
}

// ---------------------------------------------------------------------------
// Split-bf16 HMMA GEMM. C[M,N] = sum_k A[m,k]*B[n,k], A/B K-major bf16 hi/lo.
// BM=BN=128, BK=32, 256 threads (8 warps, warp tile 32x64).
// 3 passes per k-chunk: Ah*Bh + Ah*Bl + Al*Bh (fp32 accumulate).
// OUTM 0: Cf = alpha*acc (+Dadd);  OUTM 1: Chi/Clo split-bf16 out.
// DUAL: after K stages of (A,B), accumulate K2 stages of (A2,B2).
// ---------------------------------------------------------------------------
constexpr int LDS_ROW   = 40;                       // bf16 elems (80B): 5*16B -> ldmatrix conflict-free
constexpr int TILE_B    = 128 * LDS_ROW * 2;        // 10240 bytes
constexpr int STAGE_B   = 4 * TILE_B;               // Ah | Al | Bh | Bl
constexpr int SMEM_REQ  = 2 * STAGE_B;              // 81920 bytes

__device__ __forceinline__ void load_tile_async(const bf16* __restrict__ src, uint32_t smbase,
                                                int rowBase, int rlim, int ld, int k0, int tid) {
#pragma unroll
    for (int i = 0; i < 2; i++) {
        int chunk = tid * 2 + i;                // 0..511
        int row = chunk >> 2, cc = chunk & 3;   // 128 rows x 4 x 16B
        int gr = rowBase + row;
        bool ok = gr < rlim;
        const bf16* g = src + (size_t)(ok ? gr : 0) * ld + k0 + cc * 8;
        cp16(smbase + row * (LDS_ROW * 2) + cc * 16, g, ok);
    }
}

template<int OUTM, bool ADDD, bool DUAL>
__global__ __launch_bounds__(256, 1)
void gemm_mma(const bf16* __restrict__ Ah, const bf16* __restrict__ Al,
              const bf16* __restrict__ Bh, const bf16* __restrict__ Bl,
              const bf16* __restrict__ A2h, const bf16* __restrict__ A2l,
              const bf16* __restrict__ B2h, const bf16* __restrict__ B2l,
              float* __restrict__ Cf, bf16* __restrict__ Chi, bf16* __restrict__ Clo,
              const float* __restrict__ Dadd,
              int M, int N, int K, int K2, int lda, int ldb, int ldc,
              long long sA, long long sB, long long sC, float alpha)
{
    extern __shared__ char dsm[];
    const uint32_t smb = smem_u32(dsm);

    const int tid    = threadIdx.x;
    const int lane   = tid & 31;
    const int warp_m = (tid >> 5) & 3;       // 0..3 -> 32-row slices
    const int warp_n = tid >> 7;             // 0..1 -> 64-col slices

    const int bz = blockIdx.z;
    Ah += (size_t)bz * sA;  Al += (size_t)bz * sA;
    Bh += (size_t)bz * sB;  Bl += (size_t)bz * sB;
    if (DUAL) {
        A2h += (size_t)bz * sA;  A2l += (size_t)bz * sA;
        B2h += (size_t)bz * sB;  B2l += (size_t)bz * sB;
    }
    if (OUTM == 0) { Cf += (size_t)bz * sC; if (ADDD) Dadd += (size_t)bz * sC; }
    else { Chi += (size_t)bz * sC; Clo += (size_t)bz * sC; }

    const int rowBase = blockIdx.y * 128;
    const int colBase = blockIdx.x * 128;

    const int nst1 = K / 32;
    const int nst  = nst1 + (DUAL ? K2 / 32 : 0);

    float acc[64];
#pragma unroll
    for (int i = 0; i < 64; i++) acc[i] = 0.f;

    // ldmatrix source offsets (within a tile), bytes
    const uint32_t a_off = (uint32_t)((warp_m * 32 + (lane & 15)) * (LDS_ROW * 2)
                                      + (((lane >> 4) << 3)) * 2);
    const uint32_t b_off = (uint32_t)((warp_n * 64 + ((lane >> 4) << 3) + (lane & 7)) * (LDS_ROW * 2)
                                      + ((((lane >> 3) & 1) << 3)) * 2);

    auto issue_stage = [&](int s) {
        const bf16 *ah, *al, *bh, *bl; int k0;
        if (!DUAL || s < nst1) { ah = Ah;  al = Al;  bh = Bh;  bl = Bl;  k0 = s * 32; }
        else                   { ah = A2h; al = A2l; bh = B2h; bl = B2l; k0 = (s - nst1) * 32; }
        uint32_t st = smb + (s & 1) * STAGE_B;
        load_tile_async(ah, st,              rowBase, M, lda, k0, tid);
        load_tile_async(al, st + TILE_B,     rowBase, M, lda, k0, tid);
        load_tile_async(bh, st + 2 * TILE_B, colBase, N, ldb, k0, tid);
        load_tile_async(bl, st + 3 * TILE_B, colBase, N, ldb, k0, tid);
        CP_COMMIT();
    };

    issue_stage(0);

    for (int s = 0; s < nst; s++) {
        if (s + 1 < nst) { issue_stage(s + 1); CP_WAIT(1); }
        else             { CP_WAIT(0); }
        __syncthreads();

        const uint32_t st = smb + (s & 1) * STAGE_B;
#pragma unroll
        for (int kk = 0; kk < 32; kk += 16) {
            uint32_t Afh[2][4], Afl[2][4];
#pragma unroll
            for (int mi = 0; mi < 2; mi++) {
                uint32_t ao = a_off + (uint32_t)(mi * 16 * (LDS_ROW * 2) + kk * 2);
                ldm_x4(Afh[mi], st + ao);
                ldm_x4(Afl[mi], st + TILE_B + ao);
            }
#pragma unroll
            for (int nip = 0; nip < 4; nip++) {
                uint32_t Bfh[4], Bfl[4];
                uint32_t bo = b_off + (uint32_t)(nip * 16 * (LDS_ROW * 2) + kk * 2);
                ldm_x4(Bfh, st + 2 * TILE_B + bo);
                ldm_x4(Bfl, st + 3 * TILE_B + bo);
#pragma unroll
                for (int mi = 0; mi < 2; mi++) {
#pragma unroll
                    for (int half = 0; half < 2; half++) {
                        float* c = acc + ((mi * 8) + (nip * 2 + half)) * 4;
                        mma_bf16(c, Afh[mi], Bfh + half * 2);
                        mma_bf16(c, Afh[mi], Bfl + half * 2);
                        mma_bf16(c, Afl[mi], Bfh + half * 2);
                    }
                }
            }
        }
        __syncthreads();
    }

    // Epilogue: thread holds (r, c),(r, c+1) and (r+8, c),(r+8, c+1) per tile
#pragma unroll
    for (int mi = 0; mi < 2; mi++) {
#pragma unroll
        for (int ni = 0; ni < 8; ni++) {
            const float* c4 = acc + ((mi * 8) + ni) * 4;
            int r = rowBase + warp_m * 32 + mi * 16 + (lane >> 2);
            int c = colBase + warp_n * 64 + ni * 8 + (lane & 3) * 2;
            if (c >= N) continue;
#pragma unroll
            for (int h = 0; h < 2; h++) {
                int rr = r + h * 8;
                if (rr >= M) continue;
                size_t off = (size_t)rr * ldc + c;
                float v0 = c4[h * 2 + 0], v1 = c4[h * 2 + 1];
                if (OUTM == 0) {
                    v0 *= alpha; v1 *= alpha;
                    if (ADDD) {
                        float2 d2 = *reinterpret_cast<const float2*>(Dadd + off);
                        v0 += d2.x; v1 += d2.y;
                    }
                    float2 o; o.x = v0; o.y = v1;
                    *reinterpret_cast<float2*>(Cf + off) = o;
                } else {
                    bf16 h0, l0, h1, l1;
                    split2(v0, h0, l0); split2(v1, h1, l1);
                    *reinterpret_cast<__nv_bfloat162*>(Chi + off) = __nv_bfloat162(h0, h1);
                    *reinterpret_cast<__nv_bfloat162*>(Clo + off) = __nv_bfloat162(l0, l1);
                }
            }
        }
    }
}

// ---------------------------------------------------------------------------
// Conversion / elementwise kernels
// ---------------------------------------------------------------------------
__global__ __launch_bounds__(256) void cvt_split(const float* __restrict__ in,
                                                 bf16* __restrict__ hi,
                                                 bf16* __restrict__ lo, size_t n4) {
    size_t i = (size_t)blockIdx.x * 256 + threadIdx.x;
    if (i >= n4) return;
    float4 v = reinterpret_cast<const float4*>(in)[i];
    bf16 h[4], l[4];
    split2(v.x, h[0], l[0]); split2(v.y, h[1], l[1]);
    split2(v.z, h[2], l[2]); split2(v.w, h[3], l[3]);
    reinterpret_cast<__nv_bfloat162*>(hi)[i * 2 + 0] = __nv_bfloat162(h[0], h[1]);
    reinterpret_cast<__nv_bfloat162*>(hi)[i * 2 + 1] = __nv_bfloat162(h[2], h[3]);
    reinterpret_cast<__nv_bfloat162*>(lo)[i * 2 + 0] = __nv_bfloat162(l[0], l[1]);
    reinterpret_cast<__nv_bfloat162*>(lo)[i * 2 + 1] = __nv_bfloat162(l[2], l[3]);
}

// gather rows: dst row r <- src row (r/NS)*LX + TMPL + r%NS, then split
__global__ __launch_bounds__(256) void cvt_gather(const float* __restrict__ in,
                                                  bf16* __restrict__ hi,
                                                  bf16* __restrict__ lo) {
    size_t i = (size_t)blockIdx.x * 256 + threadIdx.x;   // float4 index
    const size_t n4 = SZ_X / 4;
    if (i >= n4) return;
    size_t e = i * 4;
    int row = (int)(e / CH), col = (int)(e % CH);
    int b = row / NS, n = row - b * NS;
    size_t src = ((size_t)b * LX + TMPL + n) * CH + col;
    float4 v = *reinterpret_cast<const float4*>(in + src);
    bf16 h[4], l[4];
    split2(v.x, h[0], l[0]); split2(v.y, h[1], l[1]);
    split2(v.z, h[2], l[2]); split2(v.w, h[3], l[3]);
    reinterpret_cast<__nv_bfloat162*>(hi)[i * 2 + 0] = __nv_bfloat162(h[0], h[1]);
    reinterpret_cast<__nv_bfloat162*>(hi)[i * 2 + 1] = __nv_bfloat162(h[2], h[3]);
    reinterpret_cast<__nv_bfloat162*>(lo)[i * 2 + 0] = __nv_bfloat162(l[0], l[1]);
    reinterpret_cast<__nv_bfloat162*>(lo)[i * 2 + 1] = __nv_bfloat162(l[2], l[3]);
}

// transpose 768x768 weight, split to hi/lo: Wt[d][c] = W[c][d]
__global__ __launch_bounds__(256) void wt_kernel(const float* __restrict__ W,
                                                 bf16* __restrict__ hi,
                                                 bf16* __restrict__ lo) {
    __shared__ float t[32][33];
    int bx = blockIdx.x * 32, by = blockIdx.y * 32;
    int tx = threadIdx.x & 31, ty = threadIdx.x >> 5;   // 32 x 8
#pragma unroll
    for (int i = ty; i < 32; i += 8)
        t[i][tx] = W[(size_t)(by + i) * CH + bx + tx];
    __syncthreads();
#pragma unroll
    for (int i = ty; i < 32; i += 8) {
        float v = t[tx][i];
        bf16 h, l; split2(v, h, l);
        size_t o = (size_t)(bx + i) * CH + by + tx;
        hi[o] = h; lo[o] = l;
    }
}

// ---------------------------------------------------------------------------
// Block reductions / softmax / ratios / xs / layernorm
// ---------------------------------------------------------------------------
__device__ __forceinline__ float blk_red(float v, bool is_max) {
    __shared__ float red[8];
    int lane = threadIdx.x & 31, w = threadIdx.x >> 5;
#pragma unroll
    for (int o = 16; o; o >>= 1) {
        float u = __shfl_xor_sync(0xffffffffu, v, o);
        v = is_max ? fmaxf(v, u) : v + u;
    }
    if (lane == 0) red[w] = v;
    __syncthreads();
    if (w == 0) {
        v = (lane < 8) ? red[lane] : (is_max ? -3.4e38f : 0.f);
#pragma unroll
        for (int o = 4; o; o >>= 1) {
            float u = __shfl_xor_sync(0xffffffffu, v, o);
            v = is_max ? fmaxf(v, u) : v + u;
        }
        if (lane == 0) red[0] = v;
    }
    __syncthreads();
    v = red[0];
    __syncthreads();
    return v;
}

__global__ __launch_bounds__(256) void softmax_kernel(float* __restrict__ S,
                                                      bf16* __restrict__ hi,
                                                      bf16* __restrict__ lo) {
    size_t base = (size_t)blockIdx.x * NS;
    __shared__ float buf[NS];
    int tid = threadIdx.x;
    float m = -3.4e38f;
    for (int c = tid; c < NS; c += 256) { float v = S[base + c]; buf[c] = v; m = fmaxf(m, v); }
    m = blk_red(m, true);
    float s = 0.f;
    for (int c = tid; c < NS; c += 256) { float e = __expf(buf[c] - m); buf[c] = e; s += e; }
    s = blk_red(s, false);
    float inv = 1.f / s;
    for (int c = tid; c < NS; c += 256) {
        float p = buf[c] * inv;
        S[base + c] = p;
        bf16 h, l; split2(p, h, l);
        hi[base + c] = h; lo[base + c] = l;
    }
}

__global__ __launch_bounds__(256) void ratio_kernel(const float* __restrict__ S,
                                                    const float* __restrict__ Si,
                                                    float* __restrict__ s1,
                                                    float* __restrict__ s2) {
    int idx = blockIdx.x * 256 + threadIdx.x;
    if (idx >= BATCH * NS) return;
    int b = idx / NS, n = idx - b * NS;
    const float* a  = S  + (size_t)b * NT * NS + n;
    const float* ai = Si + (size_t)b * NT * NS + n;
    int pos = 0, eq = 0;
    for (int t = 0; t < NT; t++) {
        float x = a[(size_t)t * NS], y = ai[(size_t)t * NS];
        pos += (x > y);
        eq  += (x == y);
    }
    float rgb = pos * (1.f / NT), eqr = eq * (1.f / NT);
    s1[idx] = rgb + eqr;
    s2[idx] = 1.f - rgb;
}

// x_s[key][c] = s1[key]*v[key][c] + s2[key]*vi[key][c], v from VT (transposed)
__global__ __launch_bounds__(256) void xs_kernel(const bf16* __restrict__ VTh,
                                                 const bf16* __restrict__ VTl,
                                                 const bf16* __restrict__ VIh,
                                                 const bf16* __restrict__ VIl,
                                                 const float* __restrict__ s1,
                                                 const float* __restrict__ s2,
                                                 float* __restrict__ out) {
    __shared__ float tv[32][33], tw[32][33];
    int k0 = blockIdx.x * 32, c0 = blockIdx.y * 32;
    int tx = threadIdx.x & 31, ty = threadIdx.x >> 5;
#pragma unroll
    for (int i = ty; i < 32; i += 8) {
        size_t o = (size_t)(c0 + i) * MK + k0 + tx;
        tv[i][tx] = __bfloat162float(VTh[o]) + __bfloat162float(VTl[o]);
        tw[i][tx] = __bfloat162float(VIh[o]) + __bfloat162float(VIl[o]);
    }
    __syncthreads();
#pragma unroll
    for (int i = ty; i < 32; i += 8) {
        int key = k0 + i;
        float a = s1[key], b = s2[key];
        out[(size_t)key * CH + c0 + tx] = a * tv[tx][i] + b * tw[tx][i];
    }
}

__global__ __launch_bounds__(256) void ln_kernel(const float* __restrict__ U,
                                                 const float* __restrict__ gamma,
                                                 const float* __restrict__ beta,
                                                 float* __restrict__ out) {
    size_t base = (size_t)blockIdx.x * CH;
    __shared__ float buf[CH];
    int tid = threadIdx.x;
    float s = 0.f;
    for (int c = tid; c < CH; c += 256) { float v = U[base + c]; buf[c] = v; s += v; }
    s = blk_red(s, false);
    float mu = s * (1.f / CH);
    float vs = 0.f;
    for (int c = tid; c < CH; c += 256) { float d = buf[c] - mu; vs += d * d; }
    vs = blk_red(vs, false);
    float inv = rsqrtf(vs * (1.f / CH) + 1e-5f);
    for (int c = tid; c < CH; c += 256)
        out[base + c] = (buf[c] - mu) * inv * gamma[c] + beta[c];
}

// ---------------------------------------------------------------------------
// Launcher
// ---------------------------------------------------------------------------
extern "C" void kernel_launch(void* const* d_in, const int* in_sizes, int n_in,
                              void* d_out, int out_size) {
    const float* T     = (const float*)d_in[0];
    const float* x     = (const float*)d_in[1];
    const float* xi    = (const float*)d_in[2];
    const float* Wq    = (const float*)d_in[3];
    const float* Wk    = (const float*)d_in[4];
    const float* Wv    = (const float*)d_in[5];
    const float* Wout  = (const float*)d_in[6];
    const float* gamma = (const float*)d_in[7];
    const float* beta  = (const float*)d_in[8];
    float* out = (float*)d_out;

    void* bp = nullptr; cudaGetSymbolAddress(&bp, g_bf);
    void* fp = nullptr; cudaGetSymbolAddress(&fp, g_f);
    bf16*  B = (bf16*)bp;
    float* F = (float*)fp;

    cudaFuncSetAttribute(gemm_mma<0, false, false>, cudaFuncAttributeMaxDynamicSharedMemorySize, SMEM_REQ);
    cudaFuncSetAttribute(gemm_mma<0, true,  false>, cudaFuncAttributeMaxDynamicSharedMemorySize, SMEM_REQ);
    cudaFuncSetAttribute(gemm_mma<1, false, false>, cudaFuncAttributeMaxDynamicSharedMemorySize, SMEM_REQ);
    cudaFuncSetAttribute(gemm_mma<1, false, true >, cudaFuncAttributeMaxDynamicSharedMemorySize, SMEM_REQ);

    const float scale = 1.0f / sqrtf((float)CH);
    auto grid = [](int M, int N, int Z) {
        return dim3((unsigned)((N + 127) / 128), (unsigned)((M + 127) / 128), (unsigned)Z);
    };

    // 1) transpose+split weights: Wt[d][c] = W[c][d]
    dim3 wt_g(CH / 32, CH / 32);
    wt_kernel<<<wt_g, 256>>>(Wq,   B + O_WQ, B + O_WQ + SZ_W);
    wt_kernel<<<wt_g, 256>>>(Wk,   B + O_WK, B + O_WK + SZ_W);
    wt_kernel<<<wt_g, 256>>>(Wv,   B + O_WV, B + O_WV + SZ_W);
    wt_kernel<<<wt_g, 256>>>(Wout, B + O_WO, B + O_WO + SZ_W);

    // 2) split inputs
    cvt_split<<<(unsigned)(SZ_T / 4 / 256), 256>>>(T, B + O_T, B + O_T + SZ_T, SZ_T / 4);
    cvt_gather<<<(unsigned)(SZ_X / 4 / 256), 256>>>(x,  B + O_XS,  B + O_XS  + SZ_X);
    cvt_gather<<<(unsigned)(SZ_X / 4 / 256), 256>>>(xi, B + O_XIS, B + O_XIS + SZ_X);

    // 3) projections (split-bf16 outputs)
    gemm_mma<1, false, false><<<grid(MQ, CH, 1), 256, SMEM_REQ>>>(
        B + O_T, B + O_T + SZ_T, B + O_WQ, B + O_WQ + SZ_W,
        nullptr, nullptr, nullptr, nullptr,
        nullptr, B + O_Q, B + O_Q + SZ_T, nullptr,
        MQ, CH, CH, 0, CH, CH, CH, 0, 0, 0, 1.f);
    gemm_mma<1, false, false><<<grid(MK, CH, 1), 256, SMEM_REQ>>>(
        B + O_XS, B + O_XS + SZ_X, B + O_WK, B + O_WK + SZ_W,
        nullptr, nullptr, nullptr, nullptr,
        nullptr, B + O_K, B + O_K + SZ_X, nullptr,
        MK, CH, CH, 0, CH, CH, CH, 0, 0, 0, 1.f);
    gemm_mma<1, false, false><<<grid(MK, CH, 1), 256, SMEM_REQ>>>(
        B + O_XIS, B + O_XIS + SZ_X, B + O_WK, B + O_WK + SZ_W,
        nullptr, nullptr, nullptr, nullptr,
        nullptr, B + O_KI, B + O_KI + SZ_X, nullptr,
        MK, CH, CH, 0, CH, CH, CH, 0, 0, 0, 1.f);
    // VT[c][key] = sum_k WvT[c,k]*xs[key,k]   (M=CH, N=MK, ldc=MK)
    gemm_mma<1, false, false><<<grid(CH, MK, 1), 256, SMEM_REQ>>>(
        B + O_WV, B + O_WV + SZ_W, B + O_XS, B + O_XS + SZ_X,
        nullptr, nullptr, nullptr, nullptr,
        nullptr, B + O_VT, B + O_VT + SZ_X, nullptr,
        CH, MK, CH, 0, CH, CH, MK, 0, 0, 0, 1.f);
    gemm_mma<1, false, false><<<grid(CH, MK, 1), 256, SMEM_REQ>>>(
        B + O_WV, B + O_WV + SZ_W, B + O_XIS, B + O_XIS + SZ_X,
        nullptr, nullptr, nullptr, nullptr,
        nullptr, B + O_VIT, B + O_VIT + SZ_X, nullptr,
        CH, MK, CH, 0, CH, CH, MK, 0, 0, 0, 1.f);

    // 4) logits (batched): S = scale * Q @ K^T, fp32 out
    gemm_mma<0, false, false><<<grid(NT, NS, BATCH), 256, SMEM_REQ>>>(
        B + O_Q, B + O_Q + SZ_T, B + O_K, B + O_K + SZ_X,
        nullptr, nullptr, nullptr, nullptr,
        F + F_S, nullptr, nullptr, nullptr,
        NT, NS, CH, 0, CH, CH, NS,
        (long long)NT * CH, (long long)NS * CH, (long long)NT * NS, scale);
    gemm_mma<0, false, false><<<grid(NT, NS, BATCH), 256, SMEM_REQ>>>(
        B + O_Q, B + O_Q + SZ_T, B + O_KI, B + O_KI + SZ_X,
        nullptr, nullptr, nullptr, nullptr,
        F + F_SI, nullptr, nullptr, nullptr,
        NT, NS, CH, 0, CH, CH, NS,
        (long long)NT * CH, (long long)NS * CH, (long long)NT * NS, scale);

    // 5) softmax: fp32 probs in place + split-bf16 probs
    softmax_kernel<<<MQ, 256>>>(F + F_S,  B + O_SH,  B + O_SH  + SZ_S);
    softmax_kernel<<<MQ, 256>>>(F + F_SI, B + O_SIH, B + O_SIH + SZ_S);

    // 6) ratios + x_s
    ratio_kernel<<<(BATCH * NS + 255) / 256, 256>>>(F + F_S, F + F_SI, F + F_S1, F + F_S2);
    xs_kernel<<<dim3(MK / 32, CH / 32), 256>>>(
        B + O_VT, B + O_VT + SZ_X, B + O_VIT, B + O_VIT + SZ_X,
        F + F_S1, F + F_S2, out);

    // 7) P = aw @ v + awi @ vi  (DUAL accumulation, batched, split-bf16 out)
    gemm_mma<1, false, true><<<grid(NT, CH, BATCH), 256, SMEM_REQ>>>(
        B + O_SH,  B + O_SH  + SZ_S, B + O_VT,  B + O_VT  + SZ_X,
        B + O_SIH, B + O_SIH + SZ_S, B + O_VIT, B + O_VIT + SZ_X,
        nullptr, B + O_P, B + O_P + SZ_T, nullptr,
        NT, CH, NS, NS, NS, MK, CH,
        (long long)NT * NS, (long long)NS, (long long)NT * CH, 1.f);

    // 8) U = P @ Wout + T
    gemm_mma<0, true, false><<<grid(MQ, CH, 1), 256, SMEM_REQ>>>(
        B + O_P, B + O_P + SZ_T, B + O_WO, B + O_WO + SZ_W,
        nullptr, nullptr, nullptr, nullptr,
        F + F_U, nullptr, nullptr, T,
        MQ, CH, CH, 0, CH, CH, CH, 0, 0, 0, 1.f);

    // 9) T_new = LayerNorm(U)
    ln_kernel<<<MQ, 256>>>(F + F_U, gamma, beta, out + SZ_X);
}

// round 12
// speedup vs baseline: 2.2169x; 1.1836x over previous
#include <cuda_runtime.h>
#include <cuda_bf16.h>
#include <cstdint>
#include <cmath>

using bf16 = __nv_bfloat16;

// ---------------------------------------------------------------------------
// Problem constants
// ---------------------------------------------------------------------------
constexpr int BATCH = 32, NT = 320, LX = 704, CH = 768, TMPL = 128;
constexpr int NS = LX - TMPL;          // 576
constexpr int MQ = BATCH * NT;         // 10240
constexpr int MK = BATCH * NS;         // 18432

constexpr size_t SZ_T  = (size_t)MQ * CH;        // 7,864,320
constexpr size_t SZ_W  = (size_t)CH * CH;        // 589,824
constexpr size_t SZ_X  = (size_t)MK * CH;        // 14,155,776
constexpr size_t SZ_S  = (size_t)BATCH * NT * NS;// 5,898,240
constexpr size_t SZ_R  = (size_t)BATCH * NS;     // 18,432

// bf16 pool: each logical tensor stores hi at O, lo at O+SZ.
// K/KI and VT/VIT and XS/XIS are laid out so that z-batching with stride
// 2*SZ_X selects the sibling tensor (hi/lo halves stay at +SZ_X).
constexpr size_t O_T   = 0;
constexpr size_t O_WQ  = O_T   + 2 * SZ_T;
constexpr size_t O_WK  = O_WQ  + 2 * SZ_W;
constexpr size_t O_WV  = O_WK  + 2 * SZ_W;
constexpr size_t O_WO  = O_WV  + 2 * SZ_W;
constexpr size_t O_XS  = O_WO  + 2 * SZ_W;
constexpr size_t O_XIS = O_XS  + 2 * SZ_X;       // = O_XS + 2*SZ_X
constexpr size_t O_Q   = O_XIS + 2 * SZ_X;
constexpr size_t O_K   = O_Q   + 2 * SZ_T;
constexpr size_t O_KI  = O_K   + 2 * SZ_X;       // = O_K + 2*SZ_X
constexpr size_t O_VT  = O_KI  + 2 * SZ_X;
constexpr size_t O_VIT = O_VT  + 2 * SZ_X;       // = O_VT + 2*SZ_X
constexpr size_t O_SH  = O_VIT + 2 * SZ_X;
constexpr size_t O_SIH = O_SH  + 2 * SZ_S;
constexpr size_t O_P   = O_SIH + 2 * SZ_S;
constexpr size_t BF_TOTAL = O_P + 2 * SZ_T;

// fp32 pool (F_SI contiguous after F_S so logits can z-batch across both)
constexpr size_t F_S  = 0;
constexpr size_t F_SI = F_S  + SZ_S;
constexpr size_t F_U  = F_SI + SZ_S;
constexpr size_t F_S1 = F_U  + SZ_T;
constexpr size_t F_S2 = F_S1 + SZ_R;
constexpr size_t F_TOTAL = F_S2 + SZ_R;

__device__ bf16  g_bf[BF_TOTAL];
__device__ float g_f[F_TOTAL];

// ---------------------------------------------------------------------------
// PTX helpers (sm_80-level: legal on the harness's compute_103 PTX target)
// ---------------------------------------------------------------------------
__device__ __forceinline__ uint32_t smem_u32(const void* p) {
    uint32_t a;
    asm("{ .reg .u64 t; cvta.to.shared.u64 t, %1; cvt.u32.u64 %0, t; }"
        : "=r"(a) : "l"(p));
    return a;
}

__device__ __forceinline__ void cp16(uint32_t dst, const void* src, bool pred) {
    int sz = pred ? 16 : 0;
    asm volatile("cp.async.cg.shared.global [%0], [%1], 16, %2;"
                 :: "r"(dst), "l"(src), "r"(sz));
}
#define CP_COMMIT() asm volatile("cp.async.commit_group;" ::: "memory")
#define CP_WAIT(N)  asm volatile("cp.async.wait_group %0;" :: "n"(N) : "memory")

__device__ __forceinline__ void ldm_x4(uint32_t* r, uint32_t addr) {
    asm volatile("ldmatrix.sync.aligned.m8n8.x4.shared.b16 {%0,%1,%2,%3}, [%4];"
                 : "=r"(r[0]), "=r"(r[1]), "=r"(r[2]), "=r"(r[3]) : "r"(addr));
}

__device__ __forceinline__ void mma_bf16(float* c, const uint32_t* a, const uint32_t* b) {
    asm volatile(
        "mma.sync.aligned.m16n8k16.row.col.f32.bf16.bf16.f32 "
        "{%0,%1,%2,%3}, {%4,%5,%6,%7}, {%8,%9}, {%0,%1,%2,%3};"
        : "+f"(c[0]), "+f"(c[1]), "+f"(c[2]), "+f"(c[3])
        : "r"(a[0]), "r"(a[1]), "r"(a[2]), "r"(a[3]), "r"(b[0]), "r"(b[1]));
}

__device__ __forceinline__ void split2(float x, bf16& h, bf16& l) {
    h = __float2bfloat16(x);
    l = __float2bfloat16(x - __bfloat162float(h));
}

// ---------------------------------------------------------------------------
// Split-bf16 HMMA GEMM. C[M,N] = sum_k A[m,k]*B[n,k], A/B K-major bf16 hi/lo.
// BM=BN=128, BK=32, 256 threads (8 warps, warp tile 32x64), 2 CTAs/SM forced.
// 3 passes per k-chunk: Ah*Bh + Ah*Bl + Al*Bh (fp32 accumulate).
// OUTM 0: Cf = alpha*acc (+Dadd);  OUTM 1: Chi/Clo split-bf16 out.
// DUAL: after K stages of (A,B), accumulate K2 stages of (A2,B2).
// ZSPLIT: z in [0,64): zz = z&31 indexes batch, z>>5 adds sB2/sC2 offsets
//         (A shared across both halves).
// ---------------------------------------------------------------------------
constexpr int LDS_ROW   = 40;                       // 80B rows: 5*16B -> ldmatrix conflict-free
constexpr int TILE_B    = 128 * LDS_ROW * 2;        // 10240 bytes
constexpr int STAGE_B   = 4 * TILE_B;               // Ah | Al | Bh | Bl
constexpr int SMEM_REQ  = 2 * STAGE_B;              // 81920 bytes (2 CTAs = 160KB/SM)

__device__ __forceinline__ void load_tile_async(const bf16* __restrict__ src, uint32_t smbase,
                                                int rowBase, int rlim, int ld, int k0, int tid) {
#pragma unroll
    for (int i = 0; i < 2; i++) {
        int chunk = tid * 2 + i;                // 0..511
        int row = chunk >> 2, cc = chunk & 3;   // 128 rows x 4 x 16B
        int gr = rowBase + row;
        bool ok = gr < rlim;
        const bf16* g = src + (size_t)(ok ? gr : 0) * ld + k0 + cc * 8;
        cp16(smbase + row * (LDS_ROW * 2) + cc * 16, g, ok);
    }
}

template<int OUTM, bool ADDD, bool DUAL, bool ZSPLIT>
__global__ __launch_bounds__(256, 2)
void gemm_mma(const bf16* __restrict__ Ah, const bf16* __restrict__ Al,
              const bf16* __restrict__ Bh, const bf16* __restrict__ Bl,
              const bf16* __restrict__ A2h, const bf16* __restrict__ A2l,
              const bf16* __restrict__ B2h, const bf16* __restrict__ B2l,
              float* __restrict__ Cf, bf16* __restrict__ Chi, bf16* __restrict__ Clo,
              const float* __restrict__ Dadd,
              int M, int N, int K, int K2, int lda, int ldb, int ldc,
              long long sA, long long sB, long long sC,
              long long sB2, long long sC2, float alpha)
{
    extern __shared__ char dsm[];
    const uint32_t smb = smem_u32(dsm);

    const int tid    = threadIdx.x;
    const int lane   = tid & 31;
    const int warp_m = (tid >> 5) & 3;       // 0..3 -> 32-row slices
    const int warp_n = tid >> 7;             // 0..1 -> 64-col slices

    const int bz = blockIdx.z;
    const int zz = ZSPLIT ? (bz & 31) : bz;
    const int hb = ZSPLIT ? (bz >> 5) : 0;
    Ah += (size_t)zz * sA;  Al += (size_t)zz * sA;
    Bh += (size_t)zz * sB + (size_t)hb * sB2;
    Bl += (size_t)zz * sB + (size_t)hb * sB2;
    if (DUAL) {
        A2h += (size_t)zz * sA;  A2l += (size_t)zz * sA;
        B2h += (size_t)zz * sB;  B2l += (size_t)zz * sB;
    }
    if (OUTM == 0) {
        Cf += (size_t)zz * sC + (size_t)hb * sC2;
        if (ADDD) Dadd += (size_t)zz * sC;
    } else {
        Chi += (size_t)zz * sC + (size_t)hb * sC2;
        Clo += (size_t)zz * sC + (size_t)hb * sC2;
    }

    const int rowBase = blockIdx.y * 128;
    const int colBase = blockIdx.x * 128;

    const int nst1 = K / 32;
    const int nst  = nst1 + (DUAL ? K2 / 32 : 0);

    float acc[64];
#pragma unroll
    for (int i = 0; i < 64; i++) acc[i] = 0.f;

    // ldmatrix source offsets (within a tile), bytes
    const uint32_t a_off = (uint32_t)((warp_m * 32 + (lane & 15)) * (LDS_ROW * 2)
                                      + (((lane >> 4) << 3)) * 2);
    const uint32_t b_off = (uint32_t)((warp_n * 64 + ((lane >> 4) << 3) + (lane & 7)) * (LDS_ROW * 2)
                                      + ((((lane >> 3) & 1) << 3)) * 2);

    auto issue_stage = [&](int s) {
        const bf16 *ah, *al, *bh, *bl; int k0;
        if (!DUAL || s < nst1) { ah = Ah;  al = Al;  bh = Bh;  bl = Bl;  k0 = s * 32; }
        else                   { ah = A2h; al = A2l; bh = B2h; bl = B2l; k0 = (s - nst1) * 32; }
        uint32_t st = smb + (s & 1) * STAGE_B;
        load_tile_async(ah, st,              rowBase, M, lda, k0, tid);
        load_tile_async(al, st + TILE_B,     rowBase, M, lda, k0, tid);
        load_tile_async(bh, st + 2 * TILE_B, colBase, N, ldb, k0, tid);
        load_tile_async(bl, st + 3 * TILE_B, colBase, N, ldb, k0, tid);
        CP_COMMIT();
    };

    issue_stage(0);

    for (int s = 0; s < nst; s++) {
        if (s + 1 < nst) { issue_stage(s + 1); CP_WAIT(1); }
        else             { CP_WAIT(0); }
        __syncthreads();

        const uint32_t st = smb + (s & 1) * STAGE_B;
#pragma unroll
        for (int kk = 0; kk < 32; kk += 16) {
            uint32_t Afh[2][4], Afl[2][4];
#pragma unroll
            for (int mi = 0; mi < 2; mi++) {
                uint32_t ao = a_off + (uint32_t)(mi * 16 * (LDS_ROW * 2) + kk * 2);
                ldm_x4(Afh[mi], st + ao);
                ldm_x4(Afl[mi], st + TILE_B + ao);
            }
#pragma unroll
            for (int nip = 0; nip < 4; nip++) {
                uint32_t Bfh[4], Bfl[4];
                uint32_t bo = b_off + (uint32_t)(nip * 16 * (LDS_ROW * 2) + kk * 2);
                ldm_x4(Bfh, st + 2 * TILE_B + bo);
                ldm_x4(Bfl, st + 3 * TILE_B + bo);
#pragma unroll
                for (int mi = 0; mi < 2; mi++) {
#pragma unroll
                    for (int half = 0; half < 2; half++) {
                        float* c = acc + ((mi * 8) + (nip * 2 + half)) * 4;
                        mma_bf16(c, Afh[mi], Bfh + half * 2);
                        mma_bf16(c, Afh[mi], Bfl + half * 2);
                        mma_bf16(c, Afl[mi], Bfh + half * 2);
                    }
                }
            }
        }
        __syncthreads();
    }

    // Epilogue: thread holds (r, c),(r, c+1) and (r+8, c),(r+8, c+1) per tile
#pragma unroll
    for (int mi = 0; mi < 2; mi++) {
#pragma unroll
        for (int ni = 0; ni < 8; ni++) {
            const float* c4 = acc + ((mi * 8) + ni) * 4;
            int r = rowBase + warp_m * 32 + mi * 16 + (lane >> 2);
            int c = colBase + warp_n * 64 + ni * 8 + (lane & 3) * 2;
            if (c >= N) continue;
#pragma unroll
            for (int h = 0; h < 2; h++) {
                int rr = r + h * 8;
                if (rr >= M) continue;
                size_t off = (size_t)rr * ldc + c;
                float v0 = c4[h * 2 + 0], v1 = c4[h * 2 + 1];
                if (OUTM == 0) {
                    v0 *= alpha; v1 *= alpha;
                    if (ADDD) {
                        float2 d2 = *reinterpret_cast<const float2*>(Dadd + off);
                        v0 += d2.x; v1 += d2.y;
                    }
                    float2 o; o.x = v0; o.y = v1;
                    *reinterpret_cast<float2*>(Cf + off) = o;
                } else {
                    bf16 h0, l0, h1, l1;
                    split2(v0, h0, l0); split2(v1, h1, l1);
                    *reinterpret_cast<__nv_bfloat162*>(Chi + off) = __nv_bfloat162(h0, h1);
                    *reinterpret_cast<__nv_bfloat162*>(Clo + off) = __nv_bfloat162(l0, l1);
                }
            }
        }
    }
}

// ---------------------------------------------------------------------------
// Conversion / elementwise kernels
// ---------------------------------------------------------------------------
__global__ __launch_bounds__(256) void cvt_split(const float* __restrict__ in,
                                                 bf16* __restrict__ hi,
                                                 bf16* __restrict__ lo, size_t n4) {
    size_t i = (size_t)blockIdx.x * 256 + threadIdx.x;
    if (i >= n4) return;
    float4 v = reinterpret_cast<const float4*>(in)[i];
    bf16 h[4], l[4];
    split2(v.x, h[0], l[0]); split2(v.y, h[1], l[1]);
    split2(v.z, h[2], l[2]); split2(v.w, h[3], l[3]);
    reinterpret_cast<__nv_bfloat162*>(hi)[i * 2 + 0] = __nv_bfloat162(h[0], h[1]);
    reinterpret_cast<__nv_bfloat162*>(hi)[i * 2 + 1] = __nv_bfloat162(h[2], h[3]);
    reinterpret_cast<__nv_bfloat162*>(lo)[i * 2 + 0] = __nv_bfloat162(l[0], l[1]);
    reinterpret_cast<__nv_bfloat162*>(lo)[i * 2 + 1] = __nv_bfloat162(l[2], l[3]);
}

// gather rows: dst row r <- src row (r/NS)*LX + TMPL + r%NS, then split
__global__ __launch_bounds__(256) void cvt_gather(const float* __restrict__ in,
                                                  bf16* __restrict__ hi,
                                                  bf16* __restrict__ lo) {
    size_t i = (size_t)blockIdx.x * 256 + threadIdx.x;   // float4 index
    const size_t n4 = SZ_X / 4;
    if (i >= n4) return;
    size_t e = i * 4;
    int row = (int)(e / CH), col = (int)(e % CH);
    int b = row / NS, n = row - b * NS;
    size_t src = ((size_t)b * LX + TMPL + n) * CH + col;
    float4 v = *reinterpret_cast<const float4*>(in + src);
    bf16 h[4], l[4];
    split2(v.x, h[0], l[0]); split2(v.y, h[1], l[1]);
    split2(v.z, h[2], l[2]); split2(v.w, h[3], l[3]);
    reinterpret_cast<__nv_bfloat162*>(hi)[i * 2 + 0] = __nv_bfloat162(h[0], h[1]);
    reinterpret_cast<__nv_bfloat162*>(hi)[i * 2 + 1] = __nv_bfloat162(h[2], h[3]);
    reinterpret_cast<__nv_bfloat162*>(lo)[i * 2 + 0] = __nv_bfloat162(l[0], l[1]);
    reinterpret_cast<__nv_bfloat162*>(lo)[i * 2 + 1] = __nv_bfloat162(l[2], l[3]);
}

// transpose 768x768 weight, split to hi/lo: Wt[d][c] = W[c][d]
__global__ __launch_bounds__(256) void wt_kernel(const float* __restrict__ W,
                                                 bf16* __restrict__ hi,
                                                 bf16* __restrict__ lo) {
    __shared__ float t[32][33];
    int bx = blockIdx.x * 32, by = blockIdx.y * 32;
    int tx = threadIdx.x & 31, ty = threadIdx.x >> 5;   // 32 x 8
#pragma unroll
    for (int i = ty; i < 32; i += 8)
        t[i][tx] = W[(size_t)(by + i) * CH + bx + tx];
    __syncthreads();
#pragma unroll
    for (int i = ty; i < 32; i += 8) {
        float v = t[tx][i];
        bf16 h, l; split2(v, h, l);
        size_t o = (size_t)(bx + i) * CH + by + tx;
        hi[o] = h; lo[o] = l;
    }
}

// ---------------------------------------------------------------------------
// Block reductions / softmax / ratios / xs / layernorm
// ---------------------------------------------------------------------------
__device__ __forceinline__ float blk_red(float v, bool is_max) {
    __shared__ float red[8];
    int lane = threadIdx.x & 31, w = threadIdx.x >> 5;
#pragma unroll
    for (int o = 16; o; o >>= 1) {
        float u = __shfl_xor_sync(0xffffffffu, v, o);
        v = is_max ? fmaxf(v, u) : v + u;
    }
    if (lane == 0) red[w] = v;
    __syncthreads();
    if (w == 0) {
        v = (lane < 8) ? red[lane] : (is_max ? -3.4e38f : 0.f);
#pragma unroll
        for (int o = 4; o; o >>= 1) {
            float u = __shfl_xor_sync(0xffffffffu, v, o);
            v = is_max ? fmaxf(v, u) : v + u;
        }
        if (lane == 0) red[0] = v;
    }
    __syncthreads();
    v = red[0];
    __syncthreads();
    return v;
}

__global__ __launch_bounds__(256) void softmax_kernel(float* __restrict__ S,
                                                      bf16* __restrict__ hi,
                                                      bf16* __restrict__ lo) {
    size_t base = (size_t)blockIdx.x * NS;
    __shared__ float buf[NS];
    int tid = threadIdx.x;
    float m = -3.4e38f;
    for (int c = tid; c < NS; c += 256) { float v = S[base + c]; buf[c] = v; m = fmaxf(m, v); }
    m = blk_red(m, true);
    float s = 0.f;
    for (int c = tid; c < NS; c += 256) { float e = __expf(buf[c] - m); buf[c] = e; s += e; }
    s = blk_red(s, false);
    float inv = 1.f / s;
    for (int c = tid; c < NS; c += 256) {
        float p = buf[c] * inv;
        S[base + c] = p;
        bf16 h, l; split2(p, h, l);
        hi[base + c] = h; lo[base + c] = l;
    }
}

__global__ __launch_bounds__(256) void ratio_kernel(const float* __restrict__ S,
                                                    const float* __restrict__ Si,
                                                    float* __restrict__ s1,
                                                    float* __restrict__ s2) {
    int idx = blockIdx.x * 256 + threadIdx.x;
    if (idx >= BATCH * NS) return;
    int b = idx / NS, n = idx - b * NS;
    const float* a  = S  + (size_t)b * NT * NS + n;
    const float* ai = Si + (size_t)b * NT * NS + n;
    int pos = 0, eq = 0;
    for (int t = 0; t < NT; t++) {
        float x = a[(size_t)t * NS], y = ai[(size_t)t * NS];
        pos += (x > y);
        eq  += (x == y);
    }
    float rgb = pos * (1.f / NT), eqr = eq * (1.f / NT);
    s1[idx] = rgb + eqr;
    s2[idx] = 1.f - rgb;
}

// x_s[key][c] = s1[key]*v[key][c] + s2[key]*vi[key][c], v from VT (transposed)
__global__ __launch_bounds__(256) void xs_kernel(const bf16* __restrict__ VTh,
                                                 const bf16* __restrict__ VTl,
                                                 const bf16* __restrict__ VIh,
                                                 const bf16* __restrict__ VIl,
                                                 const float* __restrict__ s1,
                                                 const float* __restrict__ s2,
                                                 float* __restrict__ out) {
    __shared__ float tv[32][33], tw[32][33];
    int k0 = blockIdx.x * 32, c0 = blockIdx.y * 32;
    int tx = threadIdx.x & 31, ty = threadIdx.x >> 5;
#pragma unroll
    for (int i = ty; i < 32; i += 8) {
        size_t o = (size_t)(c0 + i) * MK + k0 + tx;
        tv[i][tx] = __bfloat162float(VTh[o]) + __bfloat162float(VTl[o]);
        tw[i][tx] = __bfloat162float(VIh[o]) + __bfloat162float(VIl[o]);
    }
    __syncthreads();
#pragma unroll
    for (int i = ty; i < 32; i += 8) {
        int key = k0 + i;
        float a = s1[key], b = s2[key];
        out[(size_t)key * CH + c0 + tx] = a * tv[tx][i] + b * tw[tx][i];
    }
}

__global__ __launch_bounds__(256) void ln_kernel(const float* __restrict__ U,
                                                 const float* __restrict__ gamma,
                                                 const float* __restrict__ beta,
                                                 float* __restrict__ out) {
    size_t base = (size_t)blockIdx.x * CH;
    __shared__ float buf[CH];
    int tid = threadIdx.x;
    float s = 0.f;
    for (int c = tid; c < CH; c += 256) { float v = U[base + c]; buf[c] = v; s += v; }
    s = blk_red(s, false);
    float mu = s * (1.f / CH);
    float vs = 0.f;
    for (int c = tid; c < CH; c += 256) { float d = buf[c] - mu; vs += d * d; }
    vs = blk_red(vs, false);
    float inv = rsqrtf(vs * (1.f / CH) + 1e-5f);
    for (int c = tid; c < CH; c += 256)
        out[base + c] = (buf[c] - mu) * inv * gamma[c] + beta[c];
}

// ---------------------------------------------------------------------------
// Launcher. Launch order puts the big K/KI projection GEMM at position 6 so
// the ncu capture window (-s 5 -c 1) profiles a real GEMM next round.
// ---------------------------------------------------------------------------
extern "C" void kernel_launch(void* const* d_in, const int* in_sizes, int n_in,
                              void* d_out, int out_size) {
    const float* T     = (const float*)d_in[0];
    const float* x     = (const float*)d_in[1];
    const float* xi    = (const float*)d_in[2];
    const float* Wq    = (const float*)d_in[3];
    const float* Wk    = (const float*)d_in[4];
    const float* Wv    = (const float*)d_in[5];
    const float* Wout  = (const float*)d_in[6];
    const float* gamma = (const float*)d_in[7];
    const float* beta  = (const float*)d_in[8];
    float* out = (float*)d_out;

    void* bp = nullptr; cudaGetSymbolAddress(&bp, g_bf);
    void* fp = nullptr; cudaGetSymbolAddress(&fp, g_f);
    bf16*  B = (bf16*)bp;
    float* F = (float*)fp;

    cudaFuncSetAttribute(gemm_mma<0, false, false, false>, cudaFuncAttributeMaxDynamicSharedMemorySize, SMEM_REQ);
    cudaFuncSetAttribute(gemm_mma<0, false, false, true >, cudaFuncAttributeMaxDynamicSharedMemorySize, SMEM_REQ);
    cudaFuncSetAttribute(gemm_mma<0, true,  false, false>, cudaFuncAttributeMaxDynamicSharedMemorySize, SMEM_REQ);
    cudaFuncSetAttribute(gemm_mma<1, false, false, false>, cudaFuncAttributeMaxDynamicSharedMemorySize, SMEM_REQ);
    cudaFuncSetAttribute(gemm_mma<1, false, true,  false>, cudaFuncAttributeMaxDynamicSharedMemorySize, SMEM_REQ);

    const float scale = 1.0f / sqrtf((float)CH);
    auto grid = [](int M, int N, int Z) {
        return dim3((unsigned)((N + 127) / 128), (unsigned)((M + 127) / 128), (unsigned)Z);
    };

    // --- launches 1-5: deps for the profiled GEMM ---
    dim3 wt_g(CH / 32, CH / 32);
    wt_kernel<<<wt_g, 256>>>(Wq, B + O_WQ, B + O_WQ + SZ_W);                       // 1
    wt_kernel<<<wt_g, 256>>>(Wk, B + O_WK, B + O_WK + SZ_W);                       // 2
    cvt_split<<<(unsigned)(SZ_T / 4 / 256), 256>>>(T, B + O_T, B + O_T + SZ_T, SZ_T / 4); // 3
    cvt_gather<<<(unsigned)(SZ_X / 4 / 256), 256>>>(x,  B + O_XS,  B + O_XS  + SZ_X);     // 4
    cvt_gather<<<(unsigned)(SZ_X / 4 / 256), 256>>>(xi, B + O_XIS, B + O_XIS + SZ_X);     // 5

    // --- launch 6 (PROFILED): K + KI projections, z=2 selects XS/XIS & K/KI ---
    gemm_mma<1, false, false, false><<<grid(MK, CH, 2), 256, SMEM_REQ>>>(
        B + O_XS, B + O_XS + SZ_X, B + O_WK, B + O_WK + SZ_W,
        nullptr, nullptr, nullptr, nullptr,
        nullptr, B + O_K, B + O_K + SZ_X, nullptr,
        MK, CH, CH, 0, CH, CH, CH,
        (long long)(2 * SZ_X), 0, (long long)(2 * SZ_X), 0, 0, 1.f);

    // Q = T @ Wq
    gemm_mma<1, false, false, false><<<grid(MQ, CH, 1), 256, SMEM_REQ>>>(
        B + O_T, B + O_T + SZ_T, B + O_WQ, B + O_WQ + SZ_W,
        nullptr, nullptr, nullptr, nullptr,
        nullptr, B + O_Q, B + O_Q + SZ_T, nullptr,
        MQ, CH, CH, 0, CH, CH, CH, 0, 0, 0, 0, 0, 1.f);

    // remaining weight transposes
    wt_kernel<<<wt_g, 256>>>(Wv,   B + O_WV, B + O_WV + SZ_W);
    wt_kernel<<<wt_g, 256>>>(Wout, B + O_WO, B + O_WO + SZ_W);

    // VT / VIT (transposed V): VT[c][key] = sum_k WvT[c,k]*xs[key,k]; z=2 selects XS/XIS & VT/VIT
    gemm_mma<1, false, false, false><<<grid(CH, MK, 2), 256, SMEM_REQ>>>(
        B + O_WV, B + O_WV + SZ_W, B + O_XS, B + O_XS + SZ_X,
        nullptr, nullptr, nullptr, nullptr,
        nullptr, B + O_VT, B + O_VT + SZ_X, nullptr,
        CH, MK, CH, 0, CH, CH, MK,
        0, (long long)(2 * SZ_X), (long long)(2 * SZ_X), 0, 0, 1.f);

    // logits, both sets in one launch: z in [0,64), zz=z&31 batch, z>=32 -> KI/SI
    gemm_mma<0, false, false, true><<<grid(NT, NS, 64), 256, SMEM_REQ>>>(
        B + O_Q, B + O_Q + SZ_T, B + O_K, B + O_K + SZ_X,
        nullptr, nullptr, nullptr, nullptr,
        F + F_S, nullptr, nullptr, nullptr,
        NT, NS, CH, 0, CH, CH, NS,
        (long long)NT * CH, (long long)NS * CH, (long long)NT * NS,
        (long long)(2 * SZ_X), (long long)SZ_S, scale);

    // softmax: fp32 probs in place + split-bf16 probs
    softmax_kernel<<<MQ, 256>>>(F + F_S,  B + O_SH,  B + O_SH  + SZ_S);
    softmax_kernel<<<MQ, 256>>>(F + F_SI, B + O_SIH, B + O_SIH + SZ_S);

    // ratios + x_s
    ratio_kernel<<<(BATCH * NS + 255) / 256, 256>>>(F + F_S, F + F_SI, F + F_S1, F + F_S2);
    xs_kernel<<<dim3(MK / 32, CH / 32), 256>>>(
        B + O_VT, B + O_VT + SZ_X, B + O_VIT, B + O_VIT + SZ_X,
        F + F_S1, F + F_S2, out);

    // P = aw @ v + awi @ vi  (DUAL accumulation, batched, split-bf16 out)
    gemm_mma<1, false, true, false><<<grid(NT, CH, BATCH), 256, SMEM_REQ>>>(
        B + O_SH,  B + O_SH  + SZ_S, B + O_VT,  B + O_VT  + SZ_X,
        B + O_SIH, B + O_SIH + SZ_S, B + O_VIT, B + O_VIT + SZ_X,
        nullptr, B + O_P, B + O_P + SZ_T, nullptr,
        NT, CH, NS, NS, NS, MK, CH,
        (long long)NT * NS, (long long)NS, (long long)NT * CH, 0, 0, 1.f);

    // U = P @ Wout + T
    gemm_mma<0, true, false, false><<<grid(MQ, CH, 1), 256, SMEM_REQ>>>(
        B + O_P, B + O_P + SZ_T, B + O_WO, B + O_WO + SZ_W,
        nullptr, nullptr, nullptr, nullptr,
        F + F_U, nullptr, nullptr, T,
        MQ, CH, CH, 0, CH, CH, CH, 0, 0, 0, 0, 0, 1.f);

    // T_new = LayerNorm(U)
    ln_kernel<<<MQ, 256>>>(F + F_U, gamma, beta, out + SZ_X);
}